// round 5
// baseline (speedup 1.0000x reference)
#include <cuda_runtime.h>
#include <cuda_bf16.h>
#include <math.h>

// ---------------------------------------------------------------------------
// GGNN forward:
//   per pass: z_e = (lrelu(h @ W1_e.T + b1_e)) @ W2_e.T + b2_e   (per NODE)
//             incoming[dst] += z_e[src]  for each edge in set e   (scatter)
//             h = GRU(incoming, h)
//   then segment-sum over graphs, log/nan/relu, 3-layer MLP head.
// Key restructuring: edge MLP computed per-node (100k rows) instead of
// per-edge (500k rows) -> 5x fewer GEMM FLOPs; edges become gather/scatter.
// ---------------------------------------------------------------------------

#define HD 150          // feature dim
#define LD 160          // padded leading dim (16B aligned, pad cols stay 0)
#define NMAX 100000
#define GMAX 16
#define BM 64
#define BK 32
#define KTILES 5        // 5*32 = 160 (A padded, W masked at k>=150)

static constexpr size_t GS = (size_t)NMAX * LD;   // gate buffer stride

// ---- scratch (device globals; zero-initialized at module load; pads are
//      never written after init so they remain 0 across replays) ----
__device__ float g_h  [NMAX * LD];
__device__ float g_t  [NMAX * LD];
__device__ float g_z  [NMAX * LD];
__device__ float g_inc[NMAX * LD];
__device__ float g_gate[6 * (size_t)NMAX * LD];   // ir,iz,in,hr,hz,hn
__device__ float g_graph[GMAX * HD];

// ---------------------------------------------------------------------------
// GEMM: C[M x 150] = act(A[M x 150(pad160)] @ W.T + bias), W is [150 x 150]
// row-major (out_features x in_features). ACT=1 -> leaky_relu(0.01).
// Tiling: 256 thr (16x16), BM=64 rows, full 150 cols (TN=10 w/ mask), BK=32.
// Smem layouts chosen so both loads and compute reads are bank-conflict-free.
// ---------------------------------------------------------------------------
template<int ACT>
__global__ __launch_bounds__(256, 3)
void gemm150(const float* __restrict__ A,
             const float* __restrict__ W,
             const float* __restrict__ bias,
             float* __restrict__ C, int M)
{
    __shared__ float As[BM][BK + 1];   // [row][k], LD 33 -> conflict-free
    __shared__ float Bs[LD][BK + 1];   // [col][k], LD 33 -> conflict-free

    const int tid = threadIdx.x;
    const int tx  = tid & 15;          // col group: cols tx*10 .. tx*10+9
    const int ty  = tid >> 4;          // row group: rows ty*4 .. ty*4+3
    const int row0 = blockIdx.x * BM;

    const int lk = tid & 31;           // loader: k lane
    const int lr = tid >> 5;           // loader: row/col slice (0..7)

    float acc[4][10];
    #pragma unroll
    for (int i = 0; i < 4; i++)
        #pragma unroll
        for (int j = 0; j < 10; j++) acc[i][j] = 0.f;

    #pragma unroll 1
    for (int kt = 0; kt < KTILES; kt++) {
        const int k0 = kt * BK;
        // A tile: 64 rows x 32 k (coalesced 128B rows; OOB rows -> 0)
        #pragma unroll
        for (int rr = 0; rr < 8; rr++) {
            const int r = rr * 8 + lr;
            const int grow = row0 + r;
            float v = 0.f;
            if (grow < M) v = A[(size_t)grow * LD + k0 + lk];
            As[r][lk] = v;
        }
        // W tile: 160 cols x 32 k (mask j>=150 or k>=150 -> 0)
        #pragma unroll
        for (int jj = 0; jj < 20; jj++) {
            const int j = jj * 8 + lr;
            const int k = k0 + lk;
            float v = 0.f;
            if (j < HD && k < HD) v = W[j * HD + k];
            Bs[j][lk] = v;
        }
        __syncthreads();
        #pragma unroll
        for (int k = 0; k < BK; k++) {
            float a[4], b[10];
            #pragma unroll
            for (int i = 0; i < 4; i++) a[i] = As[ty * 4 + i][k];
            #pragma unroll
            for (int j = 0; j < 10; j++) b[j] = Bs[tx * 10 + j][k];
            #pragma unroll
            for (int i = 0; i < 4; i++)
                #pragma unroll
                for (int j = 0; j < 10; j++)
                    acc[i][j] = fmaf(a[i], b[j], acc[i][j]);
        }
        __syncthreads();
    }

    #pragma unroll
    for (int i = 0; i < 4; i++) {
        const int row = row0 + ty * 4 + i;
        if (row >= M) continue;
        #pragma unroll
        for (int j = 0; j < 10; j++) {
            const int col = tx * 10 + j;
            if (col < HD) {
                float v = acc[i][j] + bias[col];
                if (ACT) v = v > 0.f ? v : 0.01f * v;
                C[(size_t)row * LD + col] = v;
            }
        }
    }
}

// ---------------------------------------------------------------------------
// Scatter: incoming[dst] += z[src], 150 floats/edge (+2 zero pads), one warp
// per edge, 16B vector reductions (red.global.add.v4.f32, sm_90+).
// ---------------------------------------------------------------------------
__global__ void scatter_add(const int* __restrict__ edges, int E,
                            const float* __restrict__ z,
                            float* __restrict__ inc)
{
    const int w = (int)((blockIdx.x * blockDim.x + threadIdx.x) >> 5);
    const int lane = threadIdx.x & 31;
    if (w >= E) return;
    const int dst = edges[2 * w + 0];
    const int src = edges[2 * w + 1];
    const float4* zr = reinterpret_cast<const float4*>(z + (size_t)src * LD);
    float4* ir = reinterpret_cast<float4*>(inc + (size_t)dst * LD);
    #pragma unroll
    for (int f = lane; f < 38; f += 32) {      // 38*4 = 152 floats (pads are 0)
        const float4 v = zr[f];
        asm volatile("red.global.add.v4.f32 [%0], {%1,%2,%3,%4};"
                     :: "l"(ir + f), "f"(v.x), "f"(v.y), "f"(v.z), "f"(v.w)
                     : "memory");
    }
}

__global__ void zero_f4(float4* __restrict__ p, int n4)
{
    int i = blockIdx.x * blockDim.x + threadIdx.x;
    const int stride = gridDim.x * blockDim.x;
    for (; i < n4; i += stride) p[i] = make_float4(0.f, 0.f, 0.f, 0.f);
}

__global__ void init_h(const float* __restrict__ nodes,
                       float* __restrict__ h, int N)
{
    int idx = blockIdx.x * blockDim.x + threadIdx.x;
    const int total = N * LD;
    const int stride = gridDim.x * blockDim.x;
    for (; idx < total; idx += stride) {
        const int r = idx / LD, c = idx - r * LD;
        h[idx] = (c < HD) ? nodes[r * HD + c] : 0.f;
    }
}

// GRU gate combine: h = (1-z)*tanh(in + r*hn) + z*h, in-place on h.
__global__ void gru_gate(const float* __restrict__ gates,
                         float* __restrict__ h, int N)
{
    int idx = blockIdx.x * blockDim.x + threadIdx.x;
    const int total = N * LD;
    const int stride = gridDim.x * blockDim.x;
    for (; idx < total; idx += stride) {
        const int c = idx % LD;
        if (c >= HD) continue;
        const float ir  = gates[0 * GS + idx];
        const float iz  = gates[1 * GS + idx];
        const float in_ = gates[2 * GS + idx];
        const float hr  = gates[3 * GS + idx];
        const float hz  = gates[4 * GS + idx];
        const float hn  = gates[5 * GS + idx];
        const float r  = 1.f / (1.f + expf(-(ir + hr)));
        const float zz = 1.f / (1.f + expf(-(iz + hz)));
        const float n  = tanhf(in_ + r * hn);
        h[idx] = (1.f - zz) * n + zz * h[idx];
    }
}

// Segment sum over sorted graph_ids: gout[gid[r]][f] += h[r][f].
__global__ void seg_sum(const float* __restrict__ h,
                        const int* __restrict__ gid,
                        float* __restrict__ gout, int N)
{
    const int f = threadIdx.x;                // 160 threads, f<150 active
    const int r0 = blockIdx.x * 256;
    const int r1 = min(r0 + 256, N);
    float acc = 0.f;
    int cur = -1;
    for (int r = r0; r < r1; r++) {
        const int id = gid[r];
        if (id != cur) {
            if (cur >= 0 && f < HD) atomicAdd(&gout[cur * HD + f], acc);
            acc = 0.f; cur = id;
        }
        if (f < HD) acc += h[(size_t)r * LD + f];
    }
    if (cur >= 0 && f < HD) atomicAdd(&gout[cur * HD + f], acc);
}

// Head: lg = log(g); nan->0; relu; concat problem_type; fc1(lrelu) ->
// fc2(lrelu) -> fcL. Tiny (16 rows): one block.
__global__ void mlp_head(const float* __restrict__ gg,      // [16][150]
                         const float* __restrict__ ptype,   // [16]
                         const float* __restrict__ fc1W, const float* __restrict__ fc1b,
                         const float* __restrict__ fc2W, const float* __restrict__ fc2b,
                         const float* __restrict__ fcLW, const float* __restrict__ fcLb,
                         float* __restrict__ out)
{
    __shared__ float sx [GMAX * 151];
    __shared__ float sy1[GMAX * 80];
    __shared__ float sy2[GMAX * 80];
    const int tid = threadIdx.x;

    for (int p = tid; p < GMAX * HD; p += blockDim.x) {
        const int g = p / HD, k = p - g * HD;
        float lg = logf(gg[p]);
        if (isnan(lg)) lg = 0.f;
        sx[g * 151 + k] = fmaxf(lg, 0.f);
    }
    for (int p = tid; p < GMAX; p += blockDim.x) sx[p * 151 + 150] = ptype[p];
    __syncthreads();

    for (int p = tid; p < GMAX * 80; p += blockDim.x) {
        const int g = p / 80, o = p - g * 80;
        float s = fc1b[o];
        for (int k = 0; k < 151; k++) s += fc1W[o * 151 + k] * sx[g * 151 + k];
        sy1[g * 80 + o] = s > 0.f ? s : 0.01f * s;
    }
    __syncthreads();

    for (int p = tid; p < GMAX * 80; p += blockDim.x) {
        const int g = p / 80, o = p - g * 80;
        float s = fc2b[o];
        for (int k = 0; k < 80; k++) s += fc2W[o * 80 + k] * sy1[g * 80 + k];
        sy2[g * 80 + o] = s > 0.f ? s : 0.01f * s;
    }
    __syncthreads();

    for (int p = tid; p < GMAX * 10; p += blockDim.x) {
        const int g = p / 10, o = p - g * 10;
        float s = fcLb[o];
        for (int k = 0; k < 80; k++) s += fcLW[o * 80 + k] * sy2[g * 80 + k];
        out[g * 10 + o] = s;
    }
}

// ---------------------------------------------------------------------------
extern "C" void kernel_launch(void* const* d_in, const int* in_sizes, int n_in,
                              void* d_out, int out_size)
{
    const float* nodes = (const float*)d_in[0];
    const float* ptype = (const float*)d_in[1];
    const float* W1_0  = (const float*)d_in[2];  const float* b1_0 = (const float*)d_in[3];
    const float* W2_0  = (const float*)d_in[4];  const float* b2_0 = (const float*)d_in[5];
    const float* W1_1  = (const float*)d_in[6];  const float* b1_1 = (const float*)d_in[7];
    const float* W2_1  = (const float*)d_in[8];  const float* b2_1 = (const float*)d_in[9];
    const float* Wih   = (const float*)d_in[10]; const float* bih  = (const float*)d_in[11];
    const float* Whh   = (const float*)d_in[12]; const float* bhh  = (const float*)d_in[13];
    const float* fc1W  = (const float*)d_in[14]; const float* fc1b = (const float*)d_in[15];
    const float* fc2W  = (const float*)d_in[16]; const float* fc2b = (const float*)d_in[17];
    const float* fcLW  = (const float*)d_in[18]; const float* fcLb = (const float*)d_in[19];
    const int* edges0  = (const int*)d_in[20];
    const int* edges1  = (const int*)d_in[21];
    const int* gids    = (const int*)d_in[22];

    const int N  = in_sizes[0] / HD;
    const int E0 = in_sizes[20] / 2;
    const int E1 = in_sizes[21] / 2;
    const int PASSES = 4;

    float *ph, *pt, *pz, *pinc, *pg, *pgraph;
    cudaGetSymbolAddress((void**)&ph,     g_h);
    cudaGetSymbolAddress((void**)&pt,     g_t);
    cudaGetSymbolAddress((void**)&pz,     g_z);
    cudaGetSymbolAddress((void**)&pinc,   g_inc);
    cudaGetSymbolAddress((void**)&pg,     g_gate);
    cudaGetSymbolAddress((void**)&pgraph, g_graph);

    const int gemmGrid = (N + BM - 1) / BM;

    init_h<<<2048, 256>>>(nodes, ph, N);

    for (int p = 0; p < PASSES; p++) {
        zero_f4<<<2048, 256>>>((float4*)pinc, N * LD / 4);

        gemm150<1><<<gemmGrid, 256>>>(ph, W1_0, b1_0, pt, N);
        gemm150<0><<<gemmGrid, 256>>>(pt, W2_0, b2_0, pz, N);
        scatter_add<<<(E0 + 7) / 8, 256>>>(edges0, E0, pz, pinc);

        gemm150<1><<<gemmGrid, 256>>>(ph, W1_1, b1_1, pt, N);
        gemm150<0><<<gemmGrid, 256>>>(pt, W2_1, b2_1, pz, N);
        scatter_add<<<(E1 + 7) / 8, 256>>>(edges1, E1, pz, pinc);

        // GRU gate GEMMs: ir,iz,in from incoming; hr,hz,hn from h
        gemm150<0><<<gemmGrid, 256>>>(pinc, Wih,              bih,          pg + 0 * GS, N);
        gemm150<0><<<gemmGrid, 256>>>(pinc, Wih + 1 * HD * HD, bih + 1 * HD, pg + 1 * GS, N);
        gemm150<0><<<gemmGrid, 256>>>(pinc, Wih + 2 * HD * HD, bih + 2 * HD, pg + 2 * GS, N);
        gemm150<0><<<gemmGrid, 256>>>(ph,   Whh,              bhh,          pg + 3 * GS, N);
        gemm150<0><<<gemmGrid, 256>>>(ph,   Whh + 1 * HD * HD, bhh + 1 * HD, pg + 4 * GS, N);
        gemm150<0><<<gemmGrid, 256>>>(ph,   Whh + 2 * HD * HD, bhh + 2 * HD, pg + 5 * GS, N);

        gru_gate<<<2048, 256>>>(pg, ph, N);
    }

    zero_f4<<<16, 256>>>((float4*)pgraph, GMAX * HD / 4);
    seg_sum<<<(N + 255) / 256, 160>>>(ph, gids, pgraph, N);
    mlp_head<<<1, 256>>>(pgraph, ptype, fc1W, fc1b, fc2W, fc2b, fcLW, fcLb,
                         (float*)d_out);
}

// round 10
// speedup vs baseline: 2.6487x; 2.6487x over previous
#include <cuda_runtime.h>
#include <cuda_bf16.h>
#include <math.h>
#include <stdint.h>

// ---------------------------------------------------------------------------
// GGNN forward. GEMMs on tensor cores via portable mma.sync (bf16, fp32 acc)
// with bf16x3 split emulation: C = Ah*Bh + Al*Bh + Ah*Bl  (residual ~2^-18).
// (tcgen05 is unavailable: harness compiles PTX for compute_103, no 'a'.)
// Persistent GEMM: W splits resident in smem, CTA grid-strides over m-tiles,
// A double-buffered via cp.async.
// ---------------------------------------------------------------------------

#define HD 150          // feature dim
#define LD 160          // padded activation leading dim (fp32)
#define NMAX 100000
#define GMAX 16
#define NMATS 10        // W1_0,W2_0,W1_1,W2_1, Wih x3, Whh x3

#define BM 64           // rows per m-tile
#define KTI 10          // k chunks of 16 (K=160, pads are zero)

// smem layout (bytes). W rows padded to 168 bf16 (336B) -> conflict-free
// ldmatrix; A rows padded to 168 floats (672B) -> conflict-free LDS.64.
#define WSTRIDE 336
#define ASTRIDE 672
#define O_WHI 0
#define O_WLO 53760                    // 160*336
#define O_A0  107520
#define O_A1  150528                   // +64*672
#define O_BIAS 193536
#define SMEM_TOTAL 194176

static constexpr size_t GS = (size_t)NMAX * LD;   // gate buffer stride

// ---- scratch (device globals, zero-initialized at module load) ----
__device__ float g_h  [NMAX * LD];
__device__ float g_t  [NMAX * LD];
__device__ float g_z  [NMAX * LD];
__device__ float g_inc[NMAX * LD];
__device__ float g_gate[6 * (size_t)NMAX * LD];   // ir,iz,in,hr,hz,hn
__device__ float g_graph[GMAX * HD];
__device__ __align__(16) __nv_bfloat16 g_Whi[NMATS * LD * LD];  // [mat][n][k]
__device__ __align__(16) __nv_bfloat16 g_Wlo[NMATS * LD * LD];

// ---------------------------------------------------------------------------
// helpers
// ---------------------------------------------------------------------------
__device__ __forceinline__ uint32_t smem_u32(const void* p) {
    uint32_t a;
    asm("{ .reg .u64 t; cvta.to.shared.u64 t, %1; cvt.u32.u64 %0, t; }"
        : "=r"(a) : "l"(p));
    return a;
}
__device__ __forceinline__ void cp16(uint32_t dst, const void* src) {
    asm volatile("cp.async.cg.shared.global [%0], [%1], 16;"
                 :: "r"(dst), "l"(src));
}
#define CP_COMMIT() asm volatile("cp.async.commit_group;" ::: "memory")
#define CP_WAIT(n)  asm volatile("cp.async.wait_group %0;" :: "n"(n) : "memory")

__device__ __forceinline__ void ldmx4(uint32_t* r, uint32_t addr) {
    asm volatile("ldmatrix.sync.aligned.m8n8.x4.shared.b16 {%0,%1,%2,%3}, [%4];"
                 : "=r"(r[0]), "=r"(r[1]), "=r"(r[2]), "=r"(r[3]) : "r"(addr));
}
__device__ __forceinline__ void mma16816(float* c, const uint32_t* a,
                                         const uint32_t* b) {
    asm volatile("mma.sync.aligned.m16n8k16.row.col.f32.bf16.bf16.f32 "
                 "{%0,%1,%2,%3}, {%4,%5,%6,%7}, {%8,%9}, {%0,%1,%2,%3};"
                 : "+f"(c[0]), "+f"(c[1]), "+f"(c[2]), "+f"(c[3])
                 : "r"(a[0]), "r"(a[1]), "r"(a[2]), "r"(a[3]),
                   "r"(b[0]), "r"(b[1]));
}
__device__ __forceinline__ uint32_t f2bf2(float a, float b) {
    __nv_bfloat162 h = __floats2bfloat162_rn(a, b);   // x=a (low), y=b (high)
    return *reinterpret_cast<uint32_t*>(&h);
}
__device__ __forceinline__ uint32_t lo2(float2 v, uint32_t hi) {
    const float hx = __uint_as_float(hi << 16);
    const float hy = __uint_as_float(hi & 0xffff0000u);
    return f2bf2(v.x - hx, v.y - hy);
}

// ---------------------------------------------------------------------------
// Weight pre-split: 10 matrices -> [LD x LD] bf16 hi/lo in global ([n][k],
// k contiguous; n>=150 or k>=150 rows zero).
// ---------------------------------------------------------------------------
__global__ void make_wsplit(const float* __restrict__ W1_0, const float* __restrict__ W2_0,
                            const float* __restrict__ W1_1, const float* __restrict__ W2_1,
                            const float* __restrict__ Wih,  const float* __restrict__ Whh)
{
    const int total = NMATS * LD * LD;
    for (int idx = blockIdx.x * blockDim.x + threadIdx.x; idx < total;
         idx += gridDim.x * blockDim.x) {
        const int mat = idx / (LD * LD);
        const int rem = idx - mat * (LD * LD);
        const int r = rem / LD;
        const int k = rem - r * LD;
        float v = 0.f;
        if (r < HD && k < HD) {
            if      (mat == 0) v = W1_0[r * HD + k];
            else if (mat == 1) v = W2_0[r * HD + k];
            else if (mat == 2) v = W1_1[r * HD + k];
            else if (mat == 3) v = W2_1[r * HD + k];
            else if (mat <= 6) v = Wih[((mat - 4) * HD + r) * HD + k];
            else               v = Whh[((mat - 7) * HD + r) * HD + k];
        }
        __nv_bfloat16 hi = __float2bfloat16_rn(v);
        __nv_bfloat16 lo = __float2bfloat16_rn(v - __bfloat162float(hi));
        g_Whi[idx] = hi;
        g_Wlo[idx] = lo;
    }
}

// ---------------------------------------------------------------------------
// Persistent tensor-core GEMM:
//   C[y][M x 150(pad160)] = act(A @ W[matBase+y].T + bias[y])
// 256 threads = 8 warps as 4(m16) x 2(n80). W hi/lo resident in smem.
// A fp32 tiles double-buffered via cp.async; A frags split to bf16 hi/lo
// in registers. 3 mma products per (ntile, ktile) for bf16x3 precision.
// ---------------------------------------------------------------------------
template<int ACT>
__global__ __launch_bounds__(256, 1)
void gemm_tc(const float* __restrict__ A, int matBase,
             const float* __restrict__ bias,
             float* __restrict__ C, int M, int tiles)
{
    extern __shared__ char smem[];
    const uint32_t sb = smem_u32(smem);
    const int tid  = threadIdx.x;
    const int wid  = tid >> 5;
    const int lane = tid & 31;
    const int warpM = wid & 3;          // m16 slice within BM=64
    const int warpN = wid >> 2;         // n80 half
    const int mat = matBase + blockIdx.y;
    const float* biasp = bias + blockIdx.y * HD;
    float* Cp = C + (size_t)blockIdx.y * GS;

    // ---- resident W: cp.async hi+lo splits into smem ----
    {
        const __nv_bfloat16* Wh = g_Whi + (size_t)mat * LD * LD;
        const __nv_bfloat16* Wl = g_Wlo + (size_t)mat * LD * LD;
        for (int j = tid; j < 2 * LD * 20; j += 256) {   // 20 uint4 per row
            const int s  = (j >= LD * 20);
            const int jj = s ? (j - LD * 20) : j;
            const int r  = jj / 20;
            const int u  = jj - r * 20;
            const uint32_t dst = sb + (s ? O_WLO : O_WHI) + r * WSTRIDE + u * 16;
            const void* src = (s ? Wl : Wh) + (size_t)r * LD + u * 8;
            cp16(dst, src);
        }
        for (int c = tid; c < LD; c += 256)
            *reinterpret_cast<float*>(smem + O_BIAS + c * 4) =
                (c < HD) ? biasp[c] : 0.f;
    }

    // ---- prologue: first A tile into buf0 ----
    {
        const int t0 = blockIdx.x;
        if (t0 < tiles) {
            for (int j = tid; j < BM * 40; j += 256) {
                const int r = j / 40, u = j - r * 40;
                const int grow = min(t0 * BM + r, M - 1);
                cp16(sb + O_A0 + r * ASTRIDE + u * 16,
                     A + (size_t)grow * LD + u * 4);
            }
        }
        CP_COMMIT();
    }

    // per-lane ldmatrix B addresses (5 ntile-pairs), kt advances by 32B
    const int gB = lane >> 3;
    const int rB = (lane & 7) + ((gB >> 1) << 3);
    const int kB = (gB & 1) << 3;
    uint32_t bAddr[5];
    #pragma unroll
    for (int p = 0; p < 5; p++)
        bAddr[p] = sb + O_WHI + (warpN * 80 + p * 16 + rB) * WSTRIDE + kB * 2;

    const int rowA = warpM * 16 + (lane >> 2);
    const int kA   = (lane & 3) * 2;

    int i = 0;
    for (int t = blockIdx.x; t < tiles; t += gridDim.x, i++) {
        const int cur = i & 1;
        const int tn = t + gridDim.x;
        if (tn < tiles) {
            const uint32_t aoff = cur ? O_A0 : O_A1;
            for (int j = tid; j < BM * 40; j += 256) {
                const int r = j / 40, u = j - r * 40;
                const int grow = min(tn * BM + r, M - 1);
                cp16(sb + aoff + r * ASTRIDE + u * 16,
                     A + (size_t)grow * LD + u * 4);
            }
            CP_COMMIT();
            CP_WAIT(1);
        } else {
            CP_WAIT(0);
        }
        __syncthreads();

        const float* sA = reinterpret_cast<const float*>(
            smem + (cur ? O_A1 : O_A0));

        float acc[10][4];
        #pragma unroll
        for (int n = 0; n < 10; n++)
            #pragma unroll
            for (int q = 0; q < 4; q++) acc[n][q] = 0.f;

        #pragma unroll
        for (int kt = 0; kt < KTI; kt++) {
            const float* ap = sA + rowA * 168 + kt * 16 + kA;
            const float2 v00 = *reinterpret_cast<const float2*>(ap);
            const float2 v10 = *reinterpret_cast<const float2*>(ap + 8 * 168);
            const float2 v01 = *reinterpret_cast<const float2*>(ap + 8);
            const float2 v11 = *reinterpret_cast<const float2*>(ap + 8 * 168 + 8);
            uint32_t ah[4], al[4];
            ah[0] = f2bf2(v00.x, v00.y);  al[0] = lo2(v00, ah[0]);
            ah[1] = f2bf2(v10.x, v10.y);  al[1] = lo2(v10, ah[1]);
            ah[2] = f2bf2(v01.x, v01.y);  al[2] = lo2(v01, ah[2]);
            ah[3] = f2bf2(v11.x, v11.y);  al[3] = lo2(v11, ah[3]);

            #pragma unroll
            for (int p = 0; p < 5; p++) {
                uint32_t bh[4], bl[4];
                ldmx4(bh, bAddr[p] + kt * 32);
                ldmx4(bl, bAddr[p] + kt * 32 + (O_WLO - O_WHI));
                mma16816(acc[2 * p],     ah, bh);
                mma16816(acc[2 * p],     al, bh);
                mma16816(acc[2 * p],     ah, bl);
                mma16816(acc[2 * p + 1], ah, bh + 2);
                mma16816(acc[2 * p + 1], al, bh + 2);
                mma16816(acc[2 * p + 1], ah, bl + 2);
            }
        }

        // ---- epilogue: bias + act, write fp32 ----
        {
            const int r0 = t * BM + warpM * 16 + (lane >> 2);
            #pragma unroll
            for (int n = 0; n < 10; n++) {
                const int c0 = warpN * 80 + n * 8 + (lane & 3) * 2;
                const float b0 = *reinterpret_cast<float*>(smem + O_BIAS + c0 * 4);
                const float b1 = *reinterpret_cast<float*>(smem + O_BIAS + (c0 + 1) * 4);
                float x0 = acc[n][0] + b0, x1 = acc[n][1] + b1;
                float x2 = acc[n][2] + b0, x3 = acc[n][3] + b1;
                if (ACT) {
                    x0 = x0 > 0.f ? x0 : 0.01f * x0;
                    x1 = x1 > 0.f ? x1 : 0.01f * x1;
                    x2 = x2 > 0.f ? x2 : 0.01f * x2;
                    x3 = x3 > 0.f ? x3 : 0.01f * x3;
                }
                if (r0 < M)
                    *reinterpret_cast<float2*>(Cp + (size_t)r0 * LD + c0) =
                        make_float2(x0, x1);
                if (r0 + 8 < M)
                    *reinterpret_cast<float2*>(Cp + (size_t)(r0 + 8) * LD + c0) =
                        make_float2(x2, x3);
            }
        }
        __syncthreads();   // protect A buffer before next issue overwrites it
    }
}

// ---------------------------------------------------------------------------
// Scatter: incoming[dst] += z[src], one warp per edge, red.global.add.v4.f32.
// ---------------------------------------------------------------------------
__global__ void scatter_add(const int* __restrict__ edges, int E,
                            const float* __restrict__ z,
                            float* __restrict__ inc)
{
    const int w = (int)((blockIdx.x * blockDim.x + threadIdx.x) >> 5);
    const int lane = threadIdx.x & 31;
    if (w >= E) return;
    const int dst = edges[2 * w + 0];
    const int src = edges[2 * w + 1];
    const float4* zr = reinterpret_cast<const float4*>(z + (size_t)src * LD);
    float4* ir = reinterpret_cast<float4*>(inc + (size_t)dst * LD);
    #pragma unroll
    for (int f = lane; f < 38; f += 32) {      // 38*4 = 152 floats (pads are 0)
        const float4 v = zr[f];
        asm volatile("red.global.add.v4.f32 [%0], {%1,%2,%3,%4};"
                     :: "l"(ir + f), "f"(v.x), "f"(v.y), "f"(v.z), "f"(v.w)
                     : "memory");
    }
}

__global__ void zero_f4(float4* __restrict__ p, int n4)
{
    int i = blockIdx.x * blockDim.x + threadIdx.x;
    const int stride = gridDim.x * blockDim.x;
    for (; i < n4; i += stride) p[i] = make_float4(0.f, 0.f, 0.f, 0.f);
}

__global__ void init_h(const float* __restrict__ nodes,
                       float* __restrict__ h, int N)
{
    int idx = blockIdx.x * blockDim.x + threadIdx.x;
    const int total = N * LD;
    const int stride = gridDim.x * blockDim.x;
    for (; idx < total; idx += stride) {
        const int r = idx / LD, c = idx - r * LD;
        h[idx] = (c < HD) ? nodes[r * HD + c] : 0.f;
    }
}

// GRU gate combine: h = (1-z)*tanh(in + r*hn) + z*h, in-place on h.
__global__ void gru_gate(const float* __restrict__ gates,
                         float* __restrict__ h, int N)
{
    int idx = blockIdx.x * blockDim.x + threadIdx.x;
    const int total = N * LD;
    const int stride = gridDim.x * blockDim.x;
    for (; idx < total; idx += stride) {
        const int c = idx % LD;
        if (c >= HD) continue;
        const float ir  = gates[0 * GS + idx];
        const float iz  = gates[1 * GS + idx];
        const float in_ = gates[2 * GS + idx];
        const float hr  = gates[3 * GS + idx];
        const float hz  = gates[4 * GS + idx];
        const float hn  = gates[5 * GS + idx];
        const float r  = 1.f / (1.f + expf(-(ir + hr)));
        const float zz = 1.f / (1.f + expf(-(iz + hz)));
        const float n  = tanhf(in_ + r * hn);
        h[idx] = (1.f - zz) * n + zz * h[idx];
    }
}

// Segment sum over sorted graph_ids.
__global__ void seg_sum(const float* __restrict__ h,
                        const int* __restrict__ gid,
                        float* __restrict__ gout, int N)
{
    const int f = threadIdx.x;
    const int r0 = blockIdx.x * 256;
    const int r1 = min(r0 + 256, N);
    float acc = 0.f;
    int cur = -1;
    for (int r = r0; r < r1; r++) {
        const int id = gid[r];
        if (id != cur) {
            if (cur >= 0 && f < HD) atomicAdd(&gout[cur * HD + f], acc);
            acc = 0.f; cur = id;
        }
        if (f < HD) acc += h[(size_t)r * LD + f];
    }
    if (cur >= 0 && f < HD) atomicAdd(&gout[cur * HD + f], acc);
}

// Head MLP (16 rows): one block.
__global__ void mlp_head(const float* __restrict__ gg,
                         const float* __restrict__ ptype,
                         const float* __restrict__ fc1W, const float* __restrict__ fc1b,
                         const float* __restrict__ fc2W, const float* __restrict__ fc2b,
                         const float* __restrict__ fcLW, const float* __restrict__ fcLb,
                         float* __restrict__ out)
{
    __shared__ float sx [GMAX * 151];
    __shared__ float sy1[GMAX * 80];
    __shared__ float sy2[GMAX * 80];
    const int tid = threadIdx.x;

    for (int p = tid; p < GMAX * HD; p += blockDim.x) {
        const int g = p / HD, k = p - g * HD;
        float lg = logf(gg[p]);
        if (isnan(lg)) lg = 0.f;
        sx[g * 151 + k] = fmaxf(lg, 0.f);
    }
    for (int p = tid; p < GMAX; p += blockDim.x) sx[p * 151 + 150] = ptype[p];
    __syncthreads();

    for (int p = tid; p < GMAX * 80; p += blockDim.x) {
        const int g = p / 80, o = p - g * 80;
        float s = fc1b[o];
        for (int k = 0; k < 151; k++) s += fc1W[o * 151 + k] * sx[g * 151 + k];
        sy1[g * 80 + o] = s > 0.f ? s : 0.01f * s;
    }
    __syncthreads();

    for (int p = tid; p < GMAX * 80; p += blockDim.x) {
        const int g = p / 80, o = p - g * 80;
        float s = fc2b[o];
        for (int k = 0; k < 80; k++) s += fc2W[o * 80 + k] * sy1[g * 80 + k];
        sy2[g * 80 + o] = s > 0.f ? s : 0.01f * s;
    }
    __syncthreads();

    for (int p = tid; p < GMAX * 10; p += blockDim.x) {
        const int g = p / 10, o = p - g * 10;
        float s = fcLb[o];
        for (int k = 0; k < 80; k++) s += fcLW[o * 80 + k] * sy2[g * 80 + k];
        out[g * 10 + o] = s;
    }
}

// ---------------------------------------------------------------------------
extern "C" void kernel_launch(void* const* d_in, const int* in_sizes, int n_in,
                              void* d_out, int out_size)
{
    const float* nodes = (const float*)d_in[0];
    const float* ptype = (const float*)d_in[1];
    const float* W1_0  = (const float*)d_in[2];  const float* b1_0 = (const float*)d_in[3];
    const float* W2_0  = (const float*)d_in[4];  const float* b2_0 = (const float*)d_in[5];
    const float* W1_1  = (const float*)d_in[6];  const float* b1_1 = (const float*)d_in[7];
    const float* W2_1  = (const float*)d_in[8];  const float* b2_1 = (const float*)d_in[9];
    const float* Wih   = (const float*)d_in[10]; const float* bih  = (const float*)d_in[11];
    const float* Whh   = (const float*)d_in[12]; const float* bhh  = (const float*)d_in[13];
    const float* fc1W  = (const float*)d_in[14]; const float* fc1b = (const float*)d_in[15];
    const float* fc2W  = (const float*)d_in[16]; const float* fc2b = (const float*)d_in[17];
    const float* fcLW  = (const float*)d_in[18]; const float* fcLb = (const float*)d_in[19];
    const int* edges0  = (const int*)d_in[20];
    const int* edges1  = (const int*)d_in[21];
    const int* gids    = (const int*)d_in[22];

    const int N  = in_sizes[0] / HD;
    const int E0 = in_sizes[20] / 2;
    const int E1 = in_sizes[21] / 2;
    const int PASSES = 4;

    float *ph, *pt, *pz, *pinc, *pg, *pgraph;
    cudaGetSymbolAddress((void**)&ph,     g_h);
    cudaGetSymbolAddress((void**)&pt,     g_t);
    cudaGetSymbolAddress((void**)&pz,     g_z);
    cudaGetSymbolAddress((void**)&pinc,   g_inc);
    cudaGetSymbolAddress((void**)&pg,     g_gate);
    cudaGetSymbolAddress((void**)&pgraph, g_graph);

    cudaFuncSetAttribute(gemm_tc<0>, cudaFuncAttributeMaxDynamicSharedMemorySize, SMEM_TOTAL);
    cudaFuncSetAttribute(gemm_tc<1>, cudaFuncAttributeMaxDynamicSharedMemorySize, SMEM_TOTAL);

    const int tiles = (N + BM - 1) / BM;

    make_wsplit<<<256, 256>>>(W1_0, W2_0, W1_1, W2_1, Wih, Whh);
    init_h<<<2048, 256>>>(nodes, ph, N);

    for (int p = 0; p < PASSES; p++) {
        zero_f4<<<2048, 256>>>((float4*)pinc, N * LD / 4);

        gemm_tc<1><<<dim3(148, 1), 256, SMEM_TOTAL>>>(ph, 0, b1_0, pt, N, tiles);
        gemm_tc<0><<<dim3(148, 1), 256, SMEM_TOTAL>>>(pt, 1, b2_0, pz, N, tiles);
        scatter_add<<<(E0 + 7) / 8, 256>>>(edges0, E0, pz, pinc);

        gemm_tc<1><<<dim3(148, 1), 256, SMEM_TOTAL>>>(ph, 2, b1_1, pt, N, tiles);
        gemm_tc<0><<<dim3(148, 1), 256, SMEM_TOTAL>>>(pt, 3, b2_1, pz, N, tiles);
        scatter_add<<<(E1 + 7) / 8, 256>>>(edges1, E1, pz, pinc);

        // GRU gates: ir,iz,in from incoming; hr,hz,hn from h (batched via grid.y)
        gemm_tc<0><<<dim3(50, 3), 256, SMEM_TOTAL>>>(pinc, 4, bih, pg,          N, tiles);
        gemm_tc<0><<<dim3(50, 3), 256, SMEM_TOTAL>>>(ph,   7, bhh, pg + 3 * GS, N, tiles);

        gru_gate<<<2048, 256>>>(pg, ph, N);
    }

    zero_f4<<<16, 256>>>((float4*)pgraph, GMAX * HD / 4);
    seg_sum<<<(N + 255) / 256, 160>>>(ph, gids, pgraph, N);
    mlp_head<<<1, 256>>>(pgraph, ptype, fc1W, fc1b, fc2W, fc2b, fcLW, fcLb,
                         (float*)d_out);
}

// round 12
// speedup vs baseline: 2.8710x; 1.0839x over previous
#include <cuda_runtime.h>
#include <cuda_bf16.h>
#include <math.h>
#include <stdint.h>

// ---------------------------------------------------------------------------
// GGNN forward. GEMMs on tensor cores via portable mma.sync (bf16, fp32 acc)
// with bf16x3 split emulation: C = Ah*Bh + Al*Bh + Ah*Bl  (residual ~2^-18).
// R10 changes:
//   * MMA reorder: product-major (10 independent MMAs between acc reuses)
//   * gate GEMM grid 49x3 (one clean wave, no 2-CTA straggler tail)
//   * edge scatter-atomics replaced by per-launch CSR build + register gather
//     (no atomics, no inc zero-fill kernel)
// ---------------------------------------------------------------------------

#define HD 150          // feature dim
#define LD 160          // padded activation leading dim (fp32)
#define NMAX 100000
#define EMAX 500000
#define GMAX 16
#define NMATS 10        // W1_0,W2_0,W1_1,W2_1, Wih x3, Whh x3

#define BM 64           // rows per m-tile
#define KTI 10          // k chunks of 16 (K=160, pads are zero)

// smem layout (bytes). W rows padded to 168 bf16 (336B) -> conflict-free
// ldmatrix; A rows padded to 168 floats (672B) -> conflict-free LDS.64.
#define WSTRIDE 336
#define ASTRIDE 672
#define O_WHI 0
#define O_WLO 53760                    // 160*336
#define O_A0  107520
#define O_A1  150528                   // +64*672
#define O_BIAS 193536
#define SMEM_TOTAL 194176

static constexpr size_t GS = (size_t)NMAX * LD;   // gate buffer stride

// ---- scratch (device globals, zero-initialized at module load) ----
__device__ float g_h  [NMAX * LD];
__device__ float g_t  [NMAX * LD];
__device__ float g_z  [NMAX * LD];
__device__ float g_inc[NMAX * LD];
__device__ float g_gate[6 * (size_t)NMAX * LD];   // ir,iz,in,hr,hz,hn
__device__ float g_graph[GMAX * HD];
__device__ __align__(16) __nv_bfloat16 g_Whi[NMATS * LD * LD];  // [mat][n][k]
__device__ __align__(16) __nv_bfloat16 g_Wlo[NMATS * LD * LD];

// CSR (rebuilt every launch; edges are static inputs)
__device__ int g_cnt [2][NMAX];
__device__ int g_off [2][NMAX + 1];
__device__ int g_cur [2][NMAX];
__device__ int g_srcs[2][EMAX];
__device__ int g_bsum[2][128];

// ---------------------------------------------------------------------------
// helpers
// ---------------------------------------------------------------------------
__device__ __forceinline__ uint32_t smem_u32(const void* p) {
    uint32_t a;
    asm("{ .reg .u64 t; cvta.to.shared.u64 t, %1; cvt.u32.u64 %0, t; }"
        : "=r"(a) : "l"(p));
    return a;
}
__device__ __forceinline__ void cp16(uint32_t dst, const void* src) {
    asm volatile("cp.async.cg.shared.global [%0], [%1], 16;"
                 :: "r"(dst), "l"(src));
}
#define CP_COMMIT() asm volatile("cp.async.commit_group;" ::: "memory")
#define CP_WAIT(n)  asm volatile("cp.async.wait_group %0;" :: "n"(n) : "memory")

__device__ __forceinline__ void ldmx4(uint32_t* r, uint32_t addr) {
    asm volatile("ldmatrix.sync.aligned.m8n8.x4.shared.b16 {%0,%1,%2,%3}, [%4];"
                 : "=r"(r[0]), "=r"(r[1]), "=r"(r[2]), "=r"(r[3]) : "r"(addr));
}
__device__ __forceinline__ void mma16816(float* c, const uint32_t* a,
                                         const uint32_t* b) {
    asm volatile("mma.sync.aligned.m16n8k16.row.col.f32.bf16.bf16.f32 "
                 "{%0,%1,%2,%3}, {%4,%5,%6,%7}, {%8,%9}, {%0,%1,%2,%3};"
                 : "+f"(c[0]), "+f"(c[1]), "+f"(c[2]), "+f"(c[3])
                 : "r"(a[0]), "r"(a[1]), "r"(a[2]), "r"(a[3]),
                   "r"(b[0]), "r"(b[1]));
}
__device__ __forceinline__ uint32_t f2bf2(float a, float b) {
    __nv_bfloat162 h = __floats2bfloat162_rn(a, b);
    return *reinterpret_cast<uint32_t*>(&h);
}
__device__ __forceinline__ uint32_t lo2(float2 v, uint32_t hi) {
    const float hx = __uint_as_float(hi << 16);
    const float hy = __uint_as_float(hi & 0xffff0000u);
    return f2bf2(v.x - hx, v.y - hy);
}

// ---------------------------------------------------------------------------
// Weight pre-split: 10 matrices -> [LD x LD] bf16 hi/lo in global.
// ---------------------------------------------------------------------------
__global__ void make_wsplit(const float* __restrict__ W1_0, const float* __restrict__ W2_0,
                            const float* __restrict__ W1_1, const float* __restrict__ W2_1,
                            const float* __restrict__ Wih,  const float* __restrict__ Whh)
{
    const int total = NMATS * LD * LD;
    for (int idx = blockIdx.x * blockDim.x + threadIdx.x; idx < total;
         idx += gridDim.x * blockDim.x) {
        const int mat = idx / (LD * LD);
        const int rem = idx - mat * (LD * LD);
        const int r = rem / LD;
        const int k = rem - r * LD;
        float v = 0.f;
        if (r < HD && k < HD) {
            if      (mat == 0) v = W1_0[r * HD + k];
            else if (mat == 1) v = W2_0[r * HD + k];
            else if (mat == 2) v = W1_1[r * HD + k];
            else if (mat == 3) v = W2_1[r * HD + k];
            else if (mat <= 6) v = Wih[((mat - 4) * HD + r) * HD + k];
            else               v = Whh[((mat - 7) * HD + r) * HD + k];
        }
        __nv_bfloat16 hi = __float2bfloat16_rn(v);
        __nv_bfloat16 lo = __float2bfloat16_rn(v - __bfloat162float(hi));
        g_Whi[idx] = hi;
        g_Wlo[idx] = lo;
    }
}

// ---------------------------------------------------------------------------
// Persistent tensor-core GEMM (same structure as R6-9, MMA order fixed):
//   C[y][M x 150(pad160)] = act(A @ W[matBase+y].T + bias[y])
// ---------------------------------------------------------------------------
template<int ACT>
__global__ __launch_bounds__(256, 1)
void gemm_tc(const float* __restrict__ A, int matBase,
             const float* __restrict__ bias,
             float* __restrict__ C, int M, int tiles)
{
    extern __shared__ char smem[];
    const uint32_t sb = smem_u32(smem);
    const int tid  = threadIdx.x;
    const int wid  = tid >> 5;
    const int lane = tid & 31;
    const int warpM = wid & 3;          // m16 slice within BM=64
    const int warpN = wid >> 2;         // n80 half
    const int mat = matBase + blockIdx.y;
    const float* biasp = bias + blockIdx.y * HD;
    float* Cp = C + (size_t)blockIdx.y * GS;

    // ---- resident W: cp.async hi+lo splits into smem ----
    {
        const __nv_bfloat16* Wh = g_Whi + (size_t)mat * LD * LD;
        const __nv_bfloat16* Wl = g_Wlo + (size_t)mat * LD * LD;
        for (int j = tid; j < 2 * LD * 20; j += 256) {   // 20 uint4 per row
            const int s  = (j >= LD * 20);
            const int jj = s ? (j - LD * 20) : j;
            const int r  = jj / 20;
            const int u  = jj - r * 20;
            const uint32_t dst = sb + (s ? O_WLO : O_WHI) + r * WSTRIDE + u * 16;
            const void* src = (s ? Wl : Wh) + (size_t)r * LD + u * 8;
            cp16(dst, src);
        }
        for (int c = tid; c < LD; c += 256)
            *reinterpret_cast<float*>(smem + O_BIAS + c * 4) =
                (c < HD) ? biasp[c] : 0.f;
    }

    // ---- prologue: first A tile into buf0 ----
    {
        const int t0 = blockIdx.x;
        if (t0 < tiles) {
            for (int j = tid; j < BM * 40; j += 256) {
                const int r = j / 40, u = j - r * 40;
                const int grow = min(t0 * BM + r, M - 1);
                cp16(sb + O_A0 + r * ASTRIDE + u * 16,
                     A + (size_t)grow * LD + u * 4);
            }
        }
        CP_COMMIT();
    }

    // per-lane ldmatrix B addresses (5 ntile-pairs), kt advances by 32B
    const int gB = lane >> 3;
    const int rB = (lane & 7) + ((gB >> 1) << 3);
    const int kB = (gB & 1) << 3;
    uint32_t bAddr[5];
    #pragma unroll
    for (int p = 0; p < 5; p++)
        bAddr[p] = sb + O_WHI + (warpN * 80 + p * 16 + rB) * WSTRIDE + kB * 2;

    const int rowA = warpM * 16 + (lane >> 2);
    const int kA   = (lane & 3) * 2;

    int i = 0;
    for (int t = blockIdx.x; t < tiles; t += gridDim.x, i++) {
        const int cur = i & 1;
        const int tn = t + gridDim.x;
        if (tn < tiles) {
            const uint32_t aoff = cur ? O_A0 : O_A1;
            for (int j = tid; j < BM * 40; j += 256) {
                const int r = j / 40, u = j - r * 40;
                const int grow = min(tn * BM + r, M - 1);
                cp16(sb + aoff + r * ASTRIDE + u * 16,
                     A + (size_t)grow * LD + u * 4);
            }
            CP_COMMIT();
            CP_WAIT(1);
        } else {
            CP_WAIT(0);
        }
        __syncthreads();

        const float* sA = reinterpret_cast<const float*>(
            smem + (cur ? O_A1 : O_A0));

        float acc[10][4];
        #pragma unroll
        for (int n = 0; n < 10; n++)
            #pragma unroll
            for (int q = 0; q < 4; q++) acc[n][q] = 0.f;

        #pragma unroll
        for (int kt = 0; kt < KTI; kt++) {
            const float* ap = sA + rowA * 168 + kt * 16 + kA;
            const float2 v00 = *reinterpret_cast<const float2*>(ap);
            const float2 v10 = *reinterpret_cast<const float2*>(ap + 8 * 168);
            const float2 v01 = *reinterpret_cast<const float2*>(ap + 8);
            const float2 v11 = *reinterpret_cast<const float2*>(ap + 8 * 168 + 8);
            uint32_t ah[4], al[4];
            ah[0] = f2bf2(v00.x, v00.y);  al[0] = lo2(v00, ah[0]);
            ah[1] = f2bf2(v10.x, v10.y);  al[1] = lo2(v10, ah[1]);
            ah[2] = f2bf2(v01.x, v01.y);  al[2] = lo2(v01, ah[2]);
            ah[3] = f2bf2(v11.x, v11.y);  al[3] = lo2(v11, ah[3]);

            // product-major order: 10 independent MMAs between reuses of the
            // same accumulator (RAW chain distance 1 -> 10).
            uint32_t bfr[5][4];
            #pragma unroll
            for (int p = 0; p < 5; p++) ldmx4(bfr[p], bAddr[p] + kt * 32);
            #pragma unroll
            for (int p = 0; p < 5; p++) {
                mma16816(acc[2 * p],     ah, bfr[p]);
                mma16816(acc[2 * p + 1], ah, bfr[p] + 2);
            }
            #pragma unroll
            for (int p = 0; p < 5; p++) {
                mma16816(acc[2 * p],     al, bfr[p]);
                mma16816(acc[2 * p + 1], al, bfr[p] + 2);
            }
            #pragma unroll
            for (int p = 0; p < 5; p++)
                ldmx4(bfr[p], bAddr[p] + kt * 32 + (O_WLO - O_WHI));
            #pragma unroll
            for (int p = 0; p < 5; p++) {
                mma16816(acc[2 * p],     ah, bfr[p]);
                mma16816(acc[2 * p + 1], ah, bfr[p] + 2);
            }
        }

        // ---- epilogue: bias + act, write fp32 ----
        {
            const int r0 = t * BM + warpM * 16 + (lane >> 2);
            #pragma unroll
            for (int n = 0; n < 10; n++) {
                const int c0 = warpN * 80 + n * 8 + (lane & 3) * 2;
                const float b0 = *reinterpret_cast<float*>(smem + O_BIAS + c0 * 4);
                const float b1 = *reinterpret_cast<float*>(smem + O_BIAS + (c0 + 1) * 4);
                float x0 = acc[n][0] + b0, x1 = acc[n][1] + b1;
                float x2 = acc[n][2] + b0, x3 = acc[n][3] + b1;
                if (ACT) {
                    x0 = x0 > 0.f ? x0 : 0.01f * x0;
                    x1 = x1 > 0.f ? x1 : 0.01f * x1;
                    x2 = x2 > 0.f ? x2 : 0.01f * x2;
                    x3 = x3 > 0.f ? x3 : 0.01f * x3;
                }
                if (r0 < M)
                    *reinterpret_cast<float2*>(Cp + (size_t)r0 * LD + c0) =
                        make_float2(x0, x1);
                if (r0 + 8 < M)
                    *reinterpret_cast<float2*>(Cp + (size_t)(r0 + 8) * LD + c0) =
                        make_float2(x2, x3);
            }
        }
        __syncthreads();   // protect A buffer before next issue overwrites it
    }
}

// ---------------------------------------------------------------------------
// CSR build (per launch; deterministic). counts -> offsets -> fill.
// ---------------------------------------------------------------------------
#define SCAN_BLK 1024
#define SCAN_NB  ((NMAX + SCAN_BLK - 1) / SCAN_BLK)   // 98

__global__ void csr_zero()
{
    int* c = &g_cnt[0][0];
    for (int i = blockIdx.x * blockDim.x + threadIdx.x; i < 2 * NMAX;
         i += gridDim.x * blockDim.x) c[i] = 0;
}
__global__ void csr_hist(const int* __restrict__ edges, int E, int s)
{
    for (int i = blockIdx.x * blockDim.x + threadIdx.x; i < E;
         i += gridDim.x * blockDim.x)
        atomicAdd(&g_cnt[s][edges[2 * i]], 1);
}
__global__ void csr_scan1(int s)
{
    __shared__ int sh[SCAN_BLK];
    const int t = threadIdx.x;
    const int idx = blockIdx.x * SCAN_BLK + t;
    int v = (idx < NMAX) ? g_cnt[s][idx] : 0;
    sh[t] = v; __syncthreads();
    #pragma unroll
    for (int d = 1; d < SCAN_BLK; d <<= 1) {
        int x = (t >= d) ? sh[t - d] : 0;
        __syncthreads();
        sh[t] += x;
        __syncthreads();
    }
    if (idx < NMAX) g_off[s][idx + 1] = sh[t];
    if (t == SCAN_BLK - 1) g_bsum[s][blockIdx.x] = sh[t];
    if (idx == 0) g_off[s][0] = 0;
}
__global__ void csr_scan2(int s)
{
    if (threadIdx.x == 0) {
        int acc = 0;
        for (int b = 0; b < SCAN_NB; b++) {
            int t = g_bsum[s][b];
            g_bsum[s][b] = acc;
            acc += t;
        }
    }
}
__global__ void csr_scan3(int s)
{
    for (int idx = blockIdx.x * blockDim.x + threadIdx.x; idx < NMAX;
         idx += gridDim.x * blockDim.x)
        g_off[s][idx + 1] += g_bsum[s][idx >> 10];
}
__global__ void csr_cursor(int s)
{
    for (int v = blockIdx.x * blockDim.x + threadIdx.x; v < NMAX;
         v += gridDim.x * blockDim.x)
        g_cur[s][v] = g_off[s][v];
}
__global__ void csr_fill(const int* __restrict__ edges, int E, int s)
{
    for (int i = blockIdx.x * blockDim.x + threadIdx.x; i < E;
         i += gridDim.x * blockDim.x) {
        const int dst = edges[2 * i];
        const int src = edges[2 * i + 1];
        const int slot = atomicAdd(&g_cur[s][dst], 1);
        g_srcs[s][slot] = src;
    }
}

// ---------------------------------------------------------------------------
// Gather: inc[v] (=/+=) sum_{e in-edges(v)} z[src(e)].  One warp per node,
// register accumulation, plain stores (no atomics). Covers all LD=160 cols
// (pads stay zero since z pads are zero).
// ---------------------------------------------------------------------------
template<int ACCUM>
__global__ void gather_add(int s, const float* __restrict__ z,
                           float* __restrict__ inc, int N)
{
    const int v = (int)((blockIdx.x * blockDim.x + threadIdx.x) >> 5);
    const int lane = threadIdx.x & 31;
    if (v >= N) return;
    const int st = g_off[s][v];
    const int en = g_off[s][v + 1];
    float4 a0 = make_float4(0.f, 0.f, 0.f, 0.f);
    float4 a1 = a0;
    for (int i = st; i < en; i++) {
        const int src = g_srcs[s][i];
        const float4* zr = reinterpret_cast<const float4*>(z + (size_t)src * LD);
        const float4 b = zr[lane];
        a0.x += b.x; a0.y += b.y; a0.z += b.z; a0.w += b.w;
        if (lane < 8) {
            const float4 c = zr[lane + 32];
            a1.x += c.x; a1.y += c.y; a1.z += c.z; a1.w += c.w;
        }
    }
    float4* ir = reinterpret_cast<float4*>(inc + (size_t)v * LD);
    if (ACCUM) {
        const float4 o = ir[lane];
        a0.x += o.x; a0.y += o.y; a0.z += o.z; a0.w += o.w;
        if (lane < 8) {
            const float4 o1 = ir[lane + 32];
            a1.x += o1.x; a1.y += o1.y; a1.z += o1.z; a1.w += o1.w;
        }
    }
    ir[lane] = a0;
    if (lane < 8) ir[lane + 32] = a1;
}

__global__ void zero_f4(float4* __restrict__ p, int n4)
{
    int i = blockIdx.x * blockDim.x + threadIdx.x;
    const int stride = gridDim.x * blockDim.x;
    for (; i < n4; i += stride) p[i] = make_float4(0.f, 0.f, 0.f, 0.f);
}

__global__ void init_h(const float* __restrict__ nodes,
                       float* __restrict__ h, int N)
{
    int idx = blockIdx.x * blockDim.x + threadIdx.x;
    const int total = N * LD;
    const int stride = gridDim.x * blockDim.x;
    for (; idx < total; idx += stride) {
        const int r = idx / LD, c = idx - r * LD;
        h[idx] = (c < HD) ? nodes[r * HD + c] : 0.f;
    }
}

// GRU gate combine: h = (1-z)*tanh(in + r*hn) + z*h, in-place on h.
__global__ void gru_gate(const float* __restrict__ gates,
                         float* __restrict__ h, int N)
{
    int idx = blockIdx.x * blockDim.x + threadIdx.x;
    const int total = N * LD;
    const int stride = gridDim.x * blockDim.x;
    for (; idx < total; idx += stride) {
        const int c = idx % LD;
        if (c >= HD) continue;
        const float ir  = gates[0 * GS + idx];
        const float iz  = gates[1 * GS + idx];
        const float in_ = gates[2 * GS + idx];
        const float hr  = gates[3 * GS + idx];
        const float hz  = gates[4 * GS + idx];
        const float hn  = gates[5 * GS + idx];
        const float r  = 1.f / (1.f + expf(-(ir + hr)));
        const float zz = 1.f / (1.f + expf(-(iz + hz)));
        const float n  = tanhf(in_ + r * hn);
        h[idx] = (1.f - zz) * n + zz * h[idx];
    }
}

// Segment sum over sorted graph_ids.
__global__ void seg_sum(const float* __restrict__ h,
                        const int* __restrict__ gid,
                        float* __restrict__ gout, int N)
{
    const int f = threadIdx.x;
    const int r0 = blockIdx.x * 256;
    const int r1 = min(r0 + 256, N);
    float acc = 0.f;
    int cur = -1;
    for (int r = r0; r < r1; r++) {
        const int id = gid[r];
        if (id != cur) {
            if (cur >= 0 && f < HD) atomicAdd(&gout[cur * HD + f], acc);
            acc = 0.f; cur = id;
        }
        if (f < HD) acc += h[(size_t)r * LD + f];
    }
    if (cur >= 0 && f < HD) atomicAdd(&gout[cur * HD + f], acc);
}

// Head MLP (16 rows): one block.
__global__ void mlp_head(const float* __restrict__ gg,
                         const float* __restrict__ ptype,
                         const float* __restrict__ fc1W, const float* __restrict__ fc1b,
                         const float* __restrict__ fc2W, const float* __restrict__ fc2b,
                         const float* __restrict__ fcLW, const float* __restrict__ fcLb,
                         float* __restrict__ out)
{
    __shared__ float sx [GMAX * 151];
    __shared__ float sy1[GMAX * 80];
    __shared__ float sy2[GMAX * 80];
    const int tid = threadIdx.x;

    for (int p = tid; p < GMAX * HD; p += blockDim.x) {
        const int g = p / HD, k = p - g * HD;
        float lg = logf(gg[p]);
        if (isnan(lg)) lg = 0.f;
        sx[g * 151 + k] = fmaxf(lg, 0.f);
    }
    for (int p = tid; p < GMAX; p += blockDim.x) sx[p * 151 + 150] = ptype[p];
    __syncthreads();

    for (int p = tid; p < GMAX * 80; p += blockDim.x) {
        const int g = p / 80, o = p - g * 80;
        float s = fc1b[o];
        for (int k = 0; k < 151; k++) s += fc1W[o * 151 + k] * sx[g * 151 + k];
        sy1[g * 80 + o] = s > 0.f ? s : 0.01f * s;
    }
    __syncthreads();

    for (int p = tid; p < GMAX * 80; p += blockDim.x) {
        const int g = p / 80, o = p - g * 80;
        float s = fc2b[o];
        for (int k = 0; k < 80; k++) s += fc2W[o * 80 + k] * sy1[g * 80 + k];
        sy2[g * 80 + o] = s > 0.f ? s : 0.01f * s;
    }
    __syncthreads();

    for (int p = tid; p < GMAX * 10; p += blockDim.x) {
        const int g = p / 10, o = p - g * 10;
        float s = fcLb[o];
        for (int k = 0; k < 80; k++) s += fcLW[o * 80 + k] * sy2[g * 80 + k];
        out[g * 10 + o] = s;
    }
}

// ---------------------------------------------------------------------------
extern "C" void kernel_launch(void* const* d_in, const int* in_sizes, int n_in,
                              void* d_out, int out_size)
{
    const float* nodes = (const float*)d_in[0];
    const float* ptype = (const float*)d_in[1];
    const float* W1_0  = (const float*)d_in[2];  const float* b1_0 = (const float*)d_in[3];
    const float* W2_0  = (const float*)d_in[4];  const float* b2_0 = (const float*)d_in[5];
    const float* W1_1  = (const float*)d_in[6];  const float* b1_1 = (const float*)d_in[7];
    const float* W2_1  = (const float*)d_in[8];  const float* b2_1 = (const float*)d_in[9];
    const float* Wih   = (const float*)d_in[10]; const float* bih  = (const float*)d_in[11];
    const float* Whh   = (const float*)d_in[12]; const float* bhh  = (const float*)d_in[13];
    const float* fc1W  = (const float*)d_in[14]; const float* fc1b = (const float*)d_in[15];
    const float* fc2W  = (const float*)d_in[16]; const float* fc2b = (const float*)d_in[17];
    const float* fcLW  = (const float*)d_in[18]; const float* fcLb = (const float*)d_in[19];
    const int* edges0  = (const int*)d_in[20];
    const int* edges1  = (const int*)d_in[21];
    const int* gids    = (const int*)d_in[22];

    const int N  = in_sizes[0] / HD;
    const int E0 = in_sizes[20] / 2;
    const int E1 = in_sizes[21] / 2;
    const int PASSES = 4;

    float *ph, *pt, *pz, *pinc, *pg, *pgraph;
    cudaGetSymbolAddress((void**)&ph,     g_h);
    cudaGetSymbolAddress((void**)&pt,     g_t);
    cudaGetSymbolAddress((void**)&pz,     g_z);
    cudaGetSymbolAddress((void**)&pinc,   g_inc);
    cudaGetSymbolAddress((void**)&pg,     g_gate);
    cudaGetSymbolAddress((void**)&pgraph, g_graph);

    cudaFuncSetAttribute(gemm_tc<0>, cudaFuncAttributeMaxDynamicSharedMemorySize, SMEM_TOTAL);
    cudaFuncSetAttribute(gemm_tc<1>, cudaFuncAttributeMaxDynamicSharedMemorySize, SMEM_TOTAL);

    const int tiles = (N + BM - 1) / BM;
    const int gatherBlocks = (N * 32 + 255) / 256;

    make_wsplit<<<256, 256>>>(W1_0, W2_0, W1_1, W2_1, Wih, Whh);
    init_h<<<2048, 256>>>(nodes, ph, N);

    // ---- CSR build (both edge sets) ----
    csr_zero<<<256, 256>>>();
    csr_hist<<<512, 256>>>(edges0, E0, 0);
    csr_hist<<<512, 256>>>(edges1, E1, 1);
    csr_scan1<<<SCAN_NB, SCAN_BLK>>>(0);
    csr_scan1<<<SCAN_NB, SCAN_BLK>>>(1);
    csr_scan2<<<1, 32>>>(0);
    csr_scan2<<<1, 32>>>(1);
    csr_scan3<<<128, 256>>>(0);
    csr_scan3<<<128, 256>>>(1);
    csr_cursor<<<128, 256>>>(0);
    csr_cursor<<<128, 256>>>(1);
    csr_fill<<<512, 256>>>(edges0, E0, 0);
    csr_fill<<<512, 256>>>(edges1, E1, 1);

    for (int p = 0; p < PASSES; p++) {
        gemm_tc<1><<<dim3(148, 1), 256, SMEM_TOTAL>>>(ph, 0, b1_0, pt, N, tiles);
        gemm_tc<0><<<dim3(148, 1), 256, SMEM_TOTAL>>>(pt, 1, b2_0, pz, N, tiles);
        gather_add<0><<<gatherBlocks, 256>>>(0, pz, pinc, N);

        gemm_tc<1><<<dim3(148, 1), 256, SMEM_TOTAL>>>(ph, 2, b1_1, pt, N, tiles);
        gemm_tc<0><<<dim3(148, 1), 256, SMEM_TOTAL>>>(pt, 3, b2_1, pz, N, tiles);
        gather_add<1><<<gatherBlocks, 256>>>(1, pz, pinc, N);

        // GRU gates: ir,iz,in from incoming; hr,hz,hn from h
        // 49x3 = 147 CTAs -> one clean wave at 1 CTA/SM (no straggler tail)
        gemm_tc<0><<<dim3(49, 3), 256, SMEM_TOTAL>>>(pinc, 4, bih, pg,          N, tiles);
        gemm_tc<0><<<dim3(49, 3), 256, SMEM_TOTAL>>>(ph,   7, bhh, pg + 3 * GS, N, tiles);

        gru_gate<<<2048, 256>>>(pg, ph, N);
    }

    zero_f4<<<16, 256>>>((float4*)pgraph, GMAX * HD / 4);
    seg_sum<<<(N + 255) / 256, 160>>>(ph, gids, pgraph, N);
    mlp_head<<<1, 256>>>(pgraph, ptype, fc1W, fc1b, fc2W, fc2b, fcLW, fcLb,
                         (float*)d_out);
}

// round 13
// speedup vs baseline: 3.0062x; 1.0471x over previous
#include <cuda_runtime.h>
#include <cuda_bf16.h>
#include <math.h>
#include <stdint.h>

// ---------------------------------------------------------------------------
// GGNN forward. GEMMs on tensor cores via portable mma.sync (bf16, fp32 acc)
// with bf16x3 split emulation: C = Ah*Bh + Al*Bh + Ah*Bl  (residual ~2^-18).
// R12 changes:
//   * gemm_multi: one launch runs several mat-GEMMs; contiguous unit ranges
//     balanced over exactly 148 CTAs (<=1 W reload per CTA)
//   * per pass: 3 GEMM launches (was 6), 1 fused gather (was 2), f4 GRU
// ---------------------------------------------------------------------------

#define HD 150          // feature dim
#define LD 160          // padded activation leading dim (fp32)
#define NMAX 100000
#define EMAX 500000
#define GMAX 16
#define NMATS 10        // W1_0,W2_0,W1_1,W2_1, Wih x3, Whh x3

#define BM 64           // rows per m-tile
#define KTI 10          // k chunks of 16 (K=160, pads are zero)

// smem layout (bytes). W rows padded to 168 bf16 (336B) -> conflict-free
// ldmatrix; A rows padded to 168 floats (672B) -> conflict-free LDS.64.
#define WSTRIDE 336
#define ASTRIDE 672
#define O_WHI 0
#define O_WLO 53760                    // 160*336
#define O_A0  107520
#define O_A1  150528                   // +64*672
#define O_BIAS 193536
#define SMEM_TOTAL 194176

static constexpr size_t GS = (size_t)NMAX * LD;   // gate buffer stride

// ---- scratch (device globals, zero-initialized at module load) ----
__device__ float g_h  [NMAX * LD];
__device__ float g_t0 [NMAX * LD];
__device__ float g_t1 [NMAX * LD];
__device__ float g_z0 [NMAX * LD];
__device__ float g_z1 [NMAX * LD];
__device__ float g_inc[NMAX * LD];
__device__ float g_gate[6 * (size_t)NMAX * LD];   // ir,iz,in,hr,hz,hn
__device__ float g_graph[GMAX * HD];
__device__ __align__(16) __nv_bfloat16 g_Whi[NMATS * LD * LD];  // [mat][n][k]
__device__ __align__(16) __nv_bfloat16 g_Wlo[NMATS * LD * LD];

// CSR (rebuilt every launch; edges are static inputs)
__device__ int g_cnt [2][NMAX];
__device__ int g_off [2][NMAX + 1];
__device__ int g_cur [2][NMAX];
__device__ int g_srcs[2][EMAX];
__device__ int g_bsum[2][128];

// ---------------------------------------------------------------------------
// helpers
// ---------------------------------------------------------------------------
__device__ __forceinline__ uint32_t smem_u32(const void* p) {
    uint32_t a;
    asm("{ .reg .u64 t; cvta.to.shared.u64 t, %1; cvt.u32.u64 %0, t; }"
        : "=r"(a) : "l"(p));
    return a;
}
__device__ __forceinline__ void cp16(uint32_t dst, const void* src) {
    asm volatile("cp.async.cg.shared.global [%0], [%1], 16;"
                 :: "r"(dst), "l"(src));
}
#define CP_COMMIT() asm volatile("cp.async.commit_group;" ::: "memory")
#define CP_WAIT(n)  asm volatile("cp.async.wait_group %0;" :: "n"(n) : "memory")

__device__ __forceinline__ void ldmx4(uint32_t* r, uint32_t addr) {
    asm volatile("ldmatrix.sync.aligned.m8n8.x4.shared.b16 {%0,%1,%2,%3}, [%4];"
                 : "=r"(r[0]), "=r"(r[1]), "=r"(r[2]), "=r"(r[3]) : "r"(addr));
}
__device__ __forceinline__ void mma16816(float* c, const uint32_t* a,
                                         const uint32_t* b) {
    asm volatile("mma.sync.aligned.m16n8k16.row.col.f32.bf16.bf16.f32 "
                 "{%0,%1,%2,%3}, {%4,%5,%6,%7}, {%8,%9}, {%0,%1,%2,%3};"
                 : "+f"(c[0]), "+f"(c[1]), "+f"(c[2]), "+f"(c[3])
                 : "r"(a[0]), "r"(a[1]), "r"(a[2]), "r"(a[3]),
                   "r"(b[0]), "r"(b[1]));
}
__device__ __forceinline__ uint32_t f2bf2(float a, float b) {
    __nv_bfloat162 h = __floats2bfloat162_rn(a, b);
    return *reinterpret_cast<uint32_t*>(&h);
}
__device__ __forceinline__ uint32_t lo2(float2 v, uint32_t hi) {
    const float hx = __uint_as_float(hi << 16);
    const float hy = __uint_as_float(hi & 0xffff0000u);
    return f2bf2(v.x - hx, v.y - hy);
}

// ---------------------------------------------------------------------------
// Weight pre-split: 10 matrices -> [LD x LD] bf16 hi/lo in global.
// ---------------------------------------------------------------------------
__global__ void make_wsplit(const float* __restrict__ W1_0, const float* __restrict__ W2_0,
                            const float* __restrict__ W1_1, const float* __restrict__ W2_1,
                            const float* __restrict__ Wih,  const float* __restrict__ Whh)
{
    const int total = NMATS * LD * LD;
    for (int idx = blockIdx.x * blockDim.x + threadIdx.x; idx < total;
         idx += gridDim.x * blockDim.x) {
        const int mat = idx / (LD * LD);
        const int rem = idx - mat * (LD * LD);
        const int r = rem / LD;
        const int k = rem - r * LD;
        float v = 0.f;
        if (r < HD && k < HD) {
            if      (mat == 0) v = W1_0[r * HD + k];
            else if (mat == 1) v = W2_0[r * HD + k];
            else if (mat == 2) v = W1_1[r * HD + k];
            else if (mat == 3) v = W2_1[r * HD + k];
            else if (mat <= 6) v = Wih[((mat - 4) * HD + r) * HD + k];
            else               v = Whh[((mat - 7) * HD + r) * HD + k];
        }
        __nv_bfloat16 hi = __float2bfloat16_rn(v);
        __nv_bfloat16 lo = __float2bfloat16_rn(v - __bfloat162float(hi));
        g_Whi[idx] = hi;
        g_Wlo[idx] = lo;
    }
}

// ---------------------------------------------------------------------------
// Multi-matrix persistent tensor-core GEMM.
//   For each job m: C[m][M x 150(pad160)] = act(A[m] @ W[mat[m]].T + bias[m])
// Work = nmats*tiles units, split into contiguous per-CTA ranges over
// gridDim.x CTAs. W hi/lo reloaded only at mat boundaries (<=1 per CTA).
// ---------------------------------------------------------------------------
struct Jobs {
    const float* A[6];
    float*       C[6];
    const float* bias[6];
    int          mat[6];
    int          nmats;
    int          act;
};

__global__ __launch_bounds__(256, 1)
void gemm_multi(Jobs j, int tiles, int M)
{
    extern __shared__ char smem[];
    const uint32_t sb = smem_u32(smem);
    const int tid  = threadIdx.x;
    const int wid  = tid >> 5;
    const int lane = tid & 31;
    const int warpM = wid & 3;          // m16 slice within BM=64
    const int warpN = wid >> 2;         // n80 half

    const int units = j.nmats * tiles;
    const int u0 = (int)(((long long)units * blockIdx.x) / gridDim.x);
    const int u1 = (int)(((long long)units * (blockIdx.x + 1)) / gridDim.x);
    if (u0 >= u1) return;

    // per-lane ldmatrix B addresses (5 ntile-pairs), kt advances by 32B
    const int gB = lane >> 3;
    const int rB = (lane & 7) + ((gB >> 1) << 3);
    const int kB = (gB & 1) << 3;
    uint32_t bAddr[5];
    #pragma unroll
    for (int p = 0; p < 5; p++)
        bAddr[p] = sb + O_WHI + (warpN * 80 + p * 16 + rB) * WSTRIDE + kB * 2;

    const int rowA = warpM * 16 + (lane >> 2);
    const int kA   = (lane & 3) * 2;

    // ---- prologue: A(u0) into buf0 ----
    {
        const int m0 = u0 / tiles, t0 = u0 - m0 * tiles;
        const float* A = j.A[m0];
        for (int jj = tid; jj < BM * 40; jj += 256) {
            const int r = jj / 40, u = jj - r * 40;
            const int grow = min(t0 * BM + r, M - 1);
            cp16(sb + O_A0 + r * ASTRIDE + u * 16, A + (size_t)grow * LD + u * 4);
        }
        CP_COMMIT();
    }

    int curMat = -1;
    int i = 0;
    for (int u = u0; u < u1; u++, i++) {
        const int m = u / tiles;
        const int t = u - m * tiles;
        const int cur = i & 1;

        if (m != curMat) {                 // (re)load W + bias for this job
            curMat = m;
            const int mat = j.mat[m];
            const __nv_bfloat16* Wh = g_Whi + (size_t)mat * LD * LD;
            const __nv_bfloat16* Wl = g_Wlo + (size_t)mat * LD * LD;
            for (int jj = tid; jj < 2 * LD * 20; jj += 256) {
                const int s  = (jj >= LD * 20);
                const int j2 = s ? (jj - LD * 20) : jj;
                const int r  = j2 / 20;
                const int uu = j2 - r * 20;
                cp16(sb + (s ? O_WLO : O_WHI) + r * WSTRIDE + uu * 16,
                     (s ? Wl : Wh) + (size_t)r * LD + uu * 8);
            }
            CP_COMMIT();
            const float* bp = j.bias[m];
            for (int c = tid; c < LD; c += 256)
                *reinterpret_cast<float*>(smem + O_BIAS + c * 4) =
                    (c < HD) ? bp[c] : 0.f;
        }

        // ---- prefetch A(u+1) into the other buffer ----
        if (u + 1 < u1) {
            const int mn = (u + 1) / tiles;
            const int tn = (u + 1) - mn * tiles;
            const float* A = j.A[mn];
            const uint32_t aoff = cur ? O_A0 : O_A1;
            for (int jj = tid; jj < BM * 40; jj += 256) {
                const int r = jj / 40, uu = jj - r * 40;
                const int grow = min(tn * BM + r, M - 1);
                cp16(sb + aoff + r * ASTRIDE + uu * 16,
                     A + (size_t)grow * LD + uu * 4);
            }
            CP_COMMIT();
            CP_WAIT(1);    // A(u) + W done; A(u+1) may stay in flight
        } else {
            CP_WAIT(0);
        }
        __syncthreads();

        const float* sA = reinterpret_cast<const float*>(
            smem + (cur ? O_A1 : O_A0));

        float acc[10][4];
        #pragma unroll
        for (int n = 0; n < 10; n++)
            #pragma unroll
            for (int q = 0; q < 4; q++) acc[n][q] = 0.f;

        #pragma unroll
        for (int kt = 0; kt < KTI; kt++) {
            const float* ap = sA + rowA * 168 + kt * 16 + kA;
            const float2 v00 = *reinterpret_cast<const float2*>(ap);
            const float2 v10 = *reinterpret_cast<const float2*>(ap + 8 * 168);
            const float2 v01 = *reinterpret_cast<const float2*>(ap + 8);
            const float2 v11 = *reinterpret_cast<const float2*>(ap + 8 * 168 + 8);
            uint32_t ah[4], al[4];
            ah[0] = f2bf2(v00.x, v00.y);  al[0] = lo2(v00, ah[0]);
            ah[1] = f2bf2(v10.x, v10.y);  al[1] = lo2(v10, ah[1]);
            ah[2] = f2bf2(v01.x, v01.y);  al[2] = lo2(v01, ah[2]);
            ah[3] = f2bf2(v11.x, v11.y);  al[3] = lo2(v11, ah[3]);

            // product-major order: 10 independent MMAs between acc reuses
            uint32_t bfr[5][4];
            #pragma unroll
            for (int p = 0; p < 5; p++) ldmx4(bfr[p], bAddr[p] + kt * 32);
            #pragma unroll
            for (int p = 0; p < 5; p++) {
                mma16816(acc[2 * p],     ah, bfr[p]);
                mma16816(acc[2 * p + 1], ah, bfr[p] + 2);
            }
            #pragma unroll
            for (int p = 0; p < 5; p++) {
                mma16816(acc[2 * p],     al, bfr[p]);
                mma16816(acc[2 * p + 1], al, bfr[p] + 2);
            }
            #pragma unroll
            for (int p = 0; p < 5; p++)
                ldmx4(bfr[p], bAddr[p] + kt * 32 + (O_WLO - O_WHI));
            #pragma unroll
            for (int p = 0; p < 5; p++) {
                mma16816(acc[2 * p],     ah, bfr[p]);
                mma16816(acc[2 * p + 1], ah, bfr[p] + 2);
            }
        }

        // ---- epilogue: bias + act, write fp32 ----
        {
            float* Cp = j.C[m];
            const int r0 = t * BM + warpM * 16 + (lane >> 2);
            #pragma unroll
            for (int n = 0; n < 10; n++) {
                const int c0 = warpN * 80 + n * 8 + (lane & 3) * 2;
                const float b0 = *reinterpret_cast<float*>(smem + O_BIAS + c0 * 4);
                const float b1 = *reinterpret_cast<float*>(smem + O_BIAS + (c0 + 1) * 4);
                float x0 = acc[n][0] + b0, x1 = acc[n][1] + b1;
                float x2 = acc[n][2] + b0, x3 = acc[n][3] + b1;
                if (j.act) {
                    x0 = x0 > 0.f ? x0 : 0.01f * x0;
                    x1 = x1 > 0.f ? x1 : 0.01f * x1;
                    x2 = x2 > 0.f ? x2 : 0.01f * x2;
                    x3 = x3 > 0.f ? x3 : 0.01f * x3;
                }
                if (r0 < M)
                    *reinterpret_cast<float2*>(Cp + (size_t)r0 * LD + c0) =
                        make_float2(x0, x1);
                if (r0 + 8 < M)
                    *reinterpret_cast<float2*>(Cp + (size_t)(r0 + 8) * LD + c0) =
                        make_float2(x2, x3);
            }
        }
        __syncthreads();   // protect A/W/bias buffers before next iteration
    }
}

// ---------------------------------------------------------------------------
// CSR build (per launch; deterministic). counts -> offsets -> fill.
// ---------------------------------------------------------------------------
#define SCAN_BLK 1024
#define SCAN_NB  ((NMAX + SCAN_BLK - 1) / SCAN_BLK)   // 98

__global__ void csr_zero()
{
    int* c = &g_cnt[0][0];
    for (int i = blockIdx.x * blockDim.x + threadIdx.x; i < 2 * NMAX;
         i += gridDim.x * blockDim.x) c[i] = 0;
}
__global__ void csr_hist(const int* __restrict__ edges, int E, int s)
{
    for (int i = blockIdx.x * blockDim.x + threadIdx.x; i < E;
         i += gridDim.x * blockDim.x)
        atomicAdd(&g_cnt[s][edges[2 * i]], 1);
}
__global__ void csr_scan1(int s)
{
    __shared__ int sh[SCAN_BLK];
    const int t = threadIdx.x;
    const int idx = blockIdx.x * SCAN_BLK + t;
    int v = (idx < NMAX) ? g_cnt[s][idx] : 0;
    sh[t] = v; __syncthreads();
    #pragma unroll
    for (int d = 1; d < SCAN_BLK; d <<= 1) {
        int x = (t >= d) ? sh[t - d] : 0;
        __syncthreads();
        sh[t] += x;
        __syncthreads();
    }
    if (idx < NMAX) g_off[s][idx + 1] = sh[t];
    if (t == SCAN_BLK - 1) g_bsum[s][blockIdx.x] = sh[t];
    if (idx == 0) g_off[s][0] = 0;
}
__global__ void csr_scan2(int s)
{
    if (threadIdx.x == 0) {
        int acc = 0;
        for (int b = 0; b < SCAN_NB; b++) {
            int t = g_bsum[s][b];
            g_bsum[s][b] = acc;
            acc += t;
        }
    }
}
__global__ void csr_scan3(int s)
{
    for (int idx = blockIdx.x * blockDim.x + threadIdx.x; idx < NMAX;
         idx += gridDim.x * blockDim.x)
        g_off[s][idx + 1] += g_bsum[s][idx >> 10];
}
__global__ void csr_cursor(int s)
{
    for (int v = blockIdx.x * blockDim.x + threadIdx.x; v < NMAX;
         v += gridDim.x * blockDim.x)
        g_cur[s][v] = g_off[s][v];
}
__global__ void csr_fill(const int* __restrict__ edges, int E, int s)
{
    for (int i = blockIdx.x * blockDim.x + threadIdx.x; i < E;
         i += gridDim.x * blockDim.x) {
        const int dst = edges[2 * i];
        const int src = edges[2 * i + 1];
        const int slot = atomicAdd(&g_cur[s][dst], 1);
        g_srcs[s][slot] = src;
    }
}

// ---------------------------------------------------------------------------
// Fused gather over BOTH edge sets:
//   inc[v] = sum_{e in set0(v)} z0[src(e)] + sum_{e in set1(v)} z1[src(e)]
// One warp per node, register accumulation, one plain store (no read).
// ---------------------------------------------------------------------------
__global__ void gather_both(const float* __restrict__ z0,
                            const float* __restrict__ z1,
                            float* __restrict__ inc, int N)
{
    const int v = (int)((blockIdx.x * blockDim.x + threadIdx.x) >> 5);
    const int lane = threadIdx.x & 31;
    if (v >= N) return;
    float4 a0 = make_float4(0.f, 0.f, 0.f, 0.f);
    float4 a1 = a0;
    #pragma unroll
    for (int s = 0; s < 2; s++) {
        const float* z = s ? z1 : z0;
        const int st = g_off[s][v];
        const int en = g_off[s][v + 1];
        for (int i = st; i < en; i++) {
            const int src = g_srcs[s][i];
            const float4* zr = reinterpret_cast<const float4*>(z + (size_t)src * LD);
            const float4 b = zr[lane];
            a0.x += b.x; a0.y += b.y; a0.z += b.z; a0.w += b.w;
            if (lane < 8) {
                const float4 c = zr[lane + 32];
                a1.x += c.x; a1.y += c.y; a1.z += c.z; a1.w += c.w;
            }
        }
    }
    float4* ir = reinterpret_cast<float4*>(inc + (size_t)v * LD);
    ir[lane] = a0;
    if (lane < 8) ir[lane + 32] = a1;
}

__global__ void zero_f4(float4* __restrict__ p, int n4)
{
    int i = blockIdx.x * blockDim.x + threadIdx.x;
    const int stride = gridDim.x * blockDim.x;
    for (; i < n4; i += stride) p[i] = make_float4(0.f, 0.f, 0.f, 0.f);
}

__global__ void init_h(const float* __restrict__ nodes,
                       float* __restrict__ h, int N)
{
    int idx = blockIdx.x * blockDim.x + threadIdx.x;
    const int total = N * LD;
    const int stride = gridDim.x * blockDim.x;
    for (; idx < total; idx += stride) {
        const int r = idx / LD, c = idx - r * LD;
        h[idx] = (c < HD) ? nodes[r * HD + c] : 0.f;
    }
}

// GRU gate combine, float4-vectorized: h = (1-z)*tanh(in + r*hn) + z*h.
// Pads: all gate pads are 0 -> h pad stays 0 (0.5*0 + 0.5*0).
__global__ void gru_gate4(const float* __restrict__ gates,
                          float* __restrict__ h, int N)
{
    const int n4 = N * (LD / 4);
    const float4* gir = reinterpret_cast<const float4*>(gates + 0 * GS);
    const float4* giz = reinterpret_cast<const float4*>(gates + 1 * GS);
    const float4* gin = reinterpret_cast<const float4*>(gates + 2 * GS);
    const float4* ghr = reinterpret_cast<const float4*>(gates + 3 * GS);
    const float4* ghz = reinterpret_cast<const float4*>(gates + 4 * GS);
    const float4* ghn = reinterpret_cast<const float4*>(gates + 5 * GS);
    float4* hp = reinterpret_cast<float4*>(h);
    int idx = blockIdx.x * blockDim.x + threadIdx.x;
    const int stride = gridDim.x * blockDim.x;
    for (; idx < n4; idx += stride) {
        const float4 ir = gir[idx], iz = giz[idx], in_ = gin[idx];
        const float4 hr = ghr[idx], hz = ghz[idx], hn = ghn[idx];
        float4 ho = hp[idx];
        #pragma unroll
        for (int c = 0; c < 4; c++) {
            const float irv = (&ir.x)[c], izv = (&iz.x)[c], inv = (&in_.x)[c];
            const float hrv = (&hr.x)[c], hzv = (&hz.x)[c], hnv = (&hn.x)[c];
            const float r  = 1.f / (1.f + expf(-(irv + hrv)));
            const float zz = 1.f / (1.f + expf(-(izv + hzv)));
            const float n  = tanhf(inv + r * hnv);
            (&ho.x)[c] = (1.f - zz) * n + zz * (&ho.x)[c];
        }
        hp[idx] = ho;
    }
}

// Segment sum over sorted graph_ids.
__global__ void seg_sum(const float* __restrict__ h,
                        const int* __restrict__ gid,
                        float* __restrict__ gout, int N)
{
    const int f = threadIdx.x;
    const int r0 = blockIdx.x * 256;
    const int r1 = min(r0 + 256, N);
    float acc = 0.f;
    int cur = -1;
    for (int r = r0; r < r1; r++) {
        const int id = gid[r];
        if (id != cur) {
            if (cur >= 0 && f < HD) atomicAdd(&gout[cur * HD + f], acc);
            acc = 0.f; cur = id;
        }
        if (f < HD) acc += h[(size_t)r * LD + f];
    }
    if (cur >= 0 && f < HD) atomicAdd(&gout[cur * HD + f], acc);
}

// Head MLP (16 rows): one block.
__global__ void mlp_head(const float* __restrict__ gg,
                         const float* __restrict__ ptype,
                         const float* __restrict__ fc1W, const float* __restrict__ fc1b,
                         const float* __restrict__ fc2W, const float* __restrict__ fc2b,
                         const float* __restrict__ fcLW, const float* __restrict__ fcLb,
                         float* __restrict__ out)
{
    __shared__ float sx [GMAX * 151];
    __shared__ float sy1[GMAX * 80];
    __shared__ float sy2[GMAX * 80];
    const int tid = threadIdx.x;

    for (int p = tid; p < GMAX * HD; p += blockDim.x) {
        const int g = p / HD, k = p - g * HD;
        float lg = logf(gg[p]);
        if (isnan(lg)) lg = 0.f;
        sx[g * 151 + k] = fmaxf(lg, 0.f);
    }
    for (int p = tid; p < GMAX; p += blockDim.x) sx[p * 151 + 150] = ptype[p];
    __syncthreads();

    for (int p = tid; p < GMAX * 80; p += blockDim.x) {
        const int g = p / 80, o = p - g * 80;
        float s = fc1b[o];
        for (int k = 0; k < 151; k++) s += fc1W[o * 151 + k] * sx[g * 151 + k];
        sy1[g * 80 + o] = s > 0.f ? s : 0.01f * s;
    }
    __syncthreads();

    for (int p = tid; p < GMAX * 80; p += blockDim.x) {
        const int g = p / 80, o = p - g * 80;
        float s = fc2b[o];
        for (int k = 0; k < 80; k++) s += fc2W[o * 80 + k] * sy1[g * 80 + k];
        sy2[g * 80 + o] = s > 0.f ? s : 0.01f * s;
    }
    __syncthreads();

    for (int p = tid; p < GMAX * 10; p += blockDim.x) {
        const int g = p / 10, o = p - g * 10;
        float s = fcLb[o];
        for (int k = 0; k < 80; k++) s += fcLW[o * 80 + k] * sy2[g * 80 + k];
        out[g * 10 + o] = s;
    }
}

// ---------------------------------------------------------------------------
extern "C" void kernel_launch(void* const* d_in, const int* in_sizes, int n_in,
                              void* d_out, int out_size)
{
    const float* nodes = (const float*)d_in[0];
    const float* ptype = (const float*)d_in[1];
    const float* W1_0  = (const float*)d_in[2];  const float* b1_0 = (const float*)d_in[3];
    const float* W2_0  = (const float*)d_in[4];  const float* b2_0 = (const float*)d_in[5];
    const float* W1_1  = (const float*)d_in[6];  const float* b1_1 = (const float*)d_in[7];
    const float* W2_1  = (const float*)d_in[8];  const float* b2_1 = (const float*)d_in[9];
    const float* Wih   = (const float*)d_in[10]; const float* bih  = (const float*)d_in[11];
    const float* Whh   = (const float*)d_in[12]; const float* bhh  = (const float*)d_in[13];
    const float* fc1W  = (const float*)d_in[14]; const float* fc1b = (const float*)d_in[15];
    const float* fc2W  = (const float*)d_in[16]; const float* fc2b = (const float*)d_in[17];
    const float* fcLW  = (const float*)d_in[18]; const float* fcLb = (const float*)d_in[19];
    const int* edges0  = (const int*)d_in[20];
    const int* edges1  = (const int*)d_in[21];
    const int* gids    = (const int*)d_in[22];

    const int N  = in_sizes[0] / HD;
    const int E0 = in_sizes[20] / 2;
    const int E1 = in_sizes[21] / 2;
    const int PASSES = 4;

    float *ph, *pt0, *pt1, *pz0, *pz1, *pinc, *pg, *pgraph;
    cudaGetSymbolAddress((void**)&ph,     g_h);
    cudaGetSymbolAddress((void**)&pt0,    g_t0);
    cudaGetSymbolAddress((void**)&pt1,    g_t1);
    cudaGetSymbolAddress((void**)&pz0,    g_z0);
    cudaGetSymbolAddress((void**)&pz1,    g_z1);
    cudaGetSymbolAddress((void**)&pinc,   g_inc);
    cudaGetSymbolAddress((void**)&pg,     g_gate);
    cudaGetSymbolAddress((void**)&pgraph, g_graph);

    cudaFuncSetAttribute(gemm_multi, cudaFuncAttributeMaxDynamicSharedMemorySize,
                         SMEM_TOTAL);

    const int tiles = (N + BM - 1) / BM;
    const int gatherBlocks = (N * 32 + 255) / 256;

    make_wsplit<<<256, 256>>>(W1_0, W2_0, W1_1, W2_1, Wih, Whh);
    init_h<<<2048, 256>>>(nodes, ph, N);

    // ---- CSR build (both edge sets) ----
    csr_zero<<<256, 256>>>();
    csr_hist<<<512, 256>>>(edges0, E0, 0);
    csr_hist<<<512, 256>>>(edges1, E1, 1);
    csr_scan1<<<SCAN_NB, SCAN_BLK>>>(0);
    csr_scan1<<<SCAN_NB, SCAN_BLK>>>(1);
    csr_scan2<<<1, 32>>>(0);
    csr_scan2<<<1, 32>>>(1);
    csr_scan3<<<128, 256>>>(0);
    csr_scan3<<<128, 256>>>(1);
    csr_cursor<<<128, 256>>>(0);
    csr_cursor<<<128, 256>>>(1);
    csr_fill<<<512, 256>>>(edges0, E0, 0);
    csr_fill<<<512, 256>>>(edges1, E1, 1);

    // ---- job tables ----
    Jobs L1 = {};      // t0 = lrelu(h W1_0^T + b1_0), t1 = lrelu(h W1_1^T + b1_1)
    L1.A[0] = ph;  L1.C[0] = pt0; L1.bias[0] = b1_0; L1.mat[0] = 0;
    L1.A[1] = ph;  L1.C[1] = pt1; L1.bias[1] = b1_1; L1.mat[1] = 2;
    L1.nmats = 2;  L1.act = 1;

    Jobs L2 = {};      // z0 = t0 W2_0^T, z1 = t1 W2_1^T, gh = h Whh^T (3 gates)
    L2.A[0] = pt0; L2.C[0] = pz0;          L2.bias[0] = b2_0;     L2.mat[0] = 1;
    L2.A[1] = pt1; L2.C[1] = pz1;          L2.bias[1] = b2_1;     L2.mat[1] = 3;
    L2.A[2] = ph;  L2.C[2] = pg + 3 * GS;  L2.bias[2] = bhh;      L2.mat[2] = 7;
    L2.A[3] = ph;  L2.C[3] = pg + 4 * GS;  L2.bias[3] = bhh + HD; L2.mat[3] = 8;
    L2.A[4] = ph;  L2.C[4] = pg + 5 * GS;  L2.bias[4] = bhh + 2 * HD; L2.mat[4] = 9;
    L2.nmats = 5;  L2.act = 0;

    Jobs L4 = {};      // gi = inc Wih^T (3 gates)
    L4.A[0] = pinc; L4.C[0] = pg + 0 * GS; L4.bias[0] = bih;          L4.mat[0] = 4;
    L4.A[1] = pinc; L4.C[1] = pg + 1 * GS; L4.bias[1] = bih + HD;     L4.mat[1] = 5;
    L4.A[2] = pinc; L4.C[2] = pg + 2 * GS; L4.bias[2] = bih + 2 * HD; L4.mat[2] = 6;
    L4.nmats = 3;  L4.act = 0;

    for (int p = 0; p < PASSES; p++) {
        gemm_multi<<<148, 256, SMEM_TOTAL>>>(L1, tiles, N);
        gemm_multi<<<148, 256, SMEM_TOTAL>>>(L2, tiles, N);
        gather_both<<<gatherBlocks, 256>>>(pz0, pz1, pinc, N);
        gemm_multi<<<148, 256, SMEM_TOTAL>>>(L4, tiles, N);
        gru_gate4<<<2048, 256>>>(pg, ph, N);
    }

    zero_f4<<<16, 256>>>((float4*)pgraph, GMAX * HD / 4);
    seg_sum<<<(N + 255) / 256, 160>>>(ph, gids, pgraph, N);
    mlp_head<<<1, 256>>>(pgraph, ptype, fc1W, fc1b, fc2W, fc2b, fcLW, fcLb,
                         (float*)d_out);
}